// round 7
// baseline (speedup 1.0000x reference)
#include <cuda_runtime.h>
#include <cstdint>

// TransferNet: B=8192 sequences, T=1024 steps, C=6 channels.
// s_j(t) = a*feats[b,t,j] + (1-a)*ln( sum_i exp( s_i(t-1)*Tn[i][j] ) )
// s(0) = feats[b,0,:], out[b,t,:] = s(t).
//
// Thread-per-batch mapping: each thread owns all 6 channels in registers,
// with the full 6x6 softmaxed transition matrix in registers. No shfl, no
// smem, no barriers. Same MUFU lane-work as the lane-split mapping (36 ex2
// + 6 lg2 per batch-step) but ~0 MIO overhead.
//
// T split into NCHUNK=8 independent 128-step chunks (map is a contraction,
// per-step error factor ~0.2; W=12 warmup -> seed error ~5e-9). 64-thread
// blocks -> 1024 blocks: a single wave on 148 SMs, ~14 warps/SM, enough to
// saturate MUFU (one warp's 42 rt-8 MUFU ops nearly fill an SMSP alone).
//
// I/O: 2 steps = 48B contiguous per thread = 3x float4 (16B-aligned at even
// t). Per-lane 128B lines are reused over ~5 steps via L1.

constexpr int T_STEPS  = 1024;
constexpr int C        = 6;
constexpr int CT       = 128;           // steps per chunk
constexpr int NCHUNK   = T_STEPS / CT;  // 8
constexpr int W        = 12;            // warmup (incl. seed), even
constexpr int ROW      = T_STEPS * C;   // 6144
constexpr int BLOCK    = 64;
constexpr float LOG2E_F = 1.4426950408889634f;
constexpr float LN2_F   = 0.6931471805599453f;

__device__ __forceinline__ float ex2f(float x) {
    float r; asm("ex2.approx.ftz.f32 %0, %1;" : "=f"(r) : "f"(x)); return r;
}
__device__ __forceinline__ float lg2f(float x) {
    float r; asm("lg2.approx.ftz.f32 %0, %1;" : "=f"(r) : "f"(x)); return r;
}

// One step, all 6 channels in-thread. t2[i*6+j] = Tn_softmax[i][j] * log2(e).
__device__ __forceinline__ void step6(float s[6], const float c[6],
                                      const float t2[36], float a, float c2) {
    float acc[6];
    #pragma unroll
    for (int j = 0; j < 6; ++j) {
        float e0 = ex2f(s[0] * t2[0 * 6 + j]);
        float e1 = ex2f(s[1] * t2[1 * 6 + j]);
        float e2 = ex2f(s[2] * t2[2 * 6 + j]);
        float e3 = ex2f(s[3] * t2[3 * 6 + j]);
        float e4 = ex2f(s[4] * t2[4 * 6 + j]);
        float e5 = ex2f(s[5] * t2[5 * 6 + j]);
        acc[j] = ((e0 + e1) + (e2 + e3)) + (e4 + e5);
    }
    #pragma unroll
    for (int j = 0; j < 6; ++j)
        s[j] = fmaf(a, c[j], c2 * lg2f(acc[j]));
}

__device__ __forceinline__ void load12(const float* p, float c[12]) {
    float4 v0 = *reinterpret_cast<const float4*>(p);
    float4 v1 = *reinterpret_cast<const float4*>(p + 4);
    float4 v2 = *reinterpret_cast<const float4*>(p + 8);
    c[0]=v0.x; c[1]=v0.y; c[2]=v0.z; c[3]=v0.w;
    c[4]=v1.x; c[5]=v1.y; c[6]=v1.z; c[7]=v1.w;
    c[8]=v2.x; c[9]=v2.y; c[10]=v2.z; c[11]=v2.w;
}
__device__ __forceinline__ void store12(float* p, const float o[12]) {
    *reinterpret_cast<float4*>(p)     = make_float4(o[0], o[1], o[2],  o[3]);
    *reinterpret_cast<float4*>(p + 4) = make_float4(o[4], o[5], o[6],  o[7]);
    *reinterpret_cast<float4*>(p + 8) = make_float4(o[8], o[9], o[10], o[11]);
}

__global__ __launch_bounds__(BLOCK, 8)
void transfer_kernel(const float* __restrict__ feats,
                     const float* __restrict__ alpha,
                     const float* __restrict__ trans,
                     float* __restrict__ out, int B)
{
    const int b = blockIdx.x * BLOCK + threadIdx.x;
    if (b >= B) return;
    const int chunk = blockIdx.y;
    const int t0 = chunk * CT;

    // a = sigmoid(alpha)
    const float av = alpha[0];
    const float a  = 1.0f / (1.0f + __expf(-av));
    const float c2 = (1.0f - a) * LN2_F;

    // Full row-softmax of transitions, scaled by log2(e). 36 registers.
    float t2[36];
    #pragma unroll
    for (int i = 0; i < 6; ++i) {
        float row[6], m = -1e30f;
        #pragma unroll
        for (int k = 0; k < 6; ++k) { row[k] = trans[i * 6 + k]; m = fmaxf(m, row[k]); }
        float sum = 0.f;
        #pragma unroll
        for (int k = 0; k < 6; ++k) { row[k] = ex2f((row[k] - m) * LOG2E_F); sum += row[k]; }
        float inv = LOG2E_F / sum;
        #pragma unroll
        for (int k = 0; k < 6; ++k) t2[i * 6 + k] = row[k] * inv;
    }

    const float* fb = feats + (size_t)b * ROW;
    float*       ob = out   + (size_t)b * ROW;

    float s[6];

    // ---- warmup (chunks > 0): seed s = feats[t0-W], run W-1 unstored steps ----
    if (chunk > 0) {
        const float* wp = fb + (size_t)(t0 - W) * C;
        float c[12];
        load12(wp, c);
        #pragma unroll
        for (int j = 0; j < 6; ++j) s[j] = c[j];
        step6(s, c + 6, t2, a, c2);
        #pragma unroll
        for (int k = 1; k < W / 2; ++k) {
            load12(wp + k * 12, c);
            step6(s, c,     t2, a, c2);
            step6(s, c + 6, t2, a, c2);
        }
    }

    // ---- main: CT steps in pairs, prefetch one pair ahead ----
    const float* rp = fb + (size_t)t0 * C;
    float*       op = ob + (size_t)t0 * C;

    float nx[12];
    load12(rp, nx);

    #pragma unroll 2
    for (int tp = 0; tp < CT; tp += 2) {
        float c[12];
        #pragma unroll
        for (int q = 0; q < 12; ++q) c[q] = nx[q];
        if (tp + 2 < CT) load12(rp + (tp + 2) * C, nx);

        float o[12];
        if (tp == 0 && chunk == 0) {
            #pragma unroll
            for (int j = 0; j < 6; ++j) s[j] = c[j];      // s(0) = feats
        } else {
            step6(s, c, t2, a, c2);
        }
        #pragma unroll
        for (int j = 0; j < 6; ++j) o[j] = s[j];

        step6(s, c + 6, t2, a, c2);
        #pragma unroll
        for (int j = 0; j < 6; ++j) o[6 + j] = s[j];

        store12(op + tp * C, o);
    }
}

extern "C" void kernel_launch(void* const* d_in, const int* in_sizes, int n_in,
                              void* d_out, int out_size) {
    const float* feats = (const float*)d_in[0];
    const float* alpha = (const float*)d_in[1];
    const float* trans = (const float*)d_in[2];
    float* out = (float*)d_out;
    (void)n_in; (void)out_size;

    int B = in_sizes[0] / (T_STEPS * C);
    dim3 grid((B + BLOCK - 1) / BLOCK, NCHUNK);
    transfer_kernel<<<grid, BLOCK>>>(feats, alpha, trans, out, B);
}